// round 3
// baseline (speedup 1.0000x reference)
#include <cuda_runtime.h>
#include <math.h>
#include <stdint.h>

#define M_TOT 16384
#define D_IN  2048
#define N_TOT 1728
#define N_PAD 1792
#define SEQ   4096

// column offsets inside a packed Y row
#define OFF_AQ 0
#define OFF_AK 128
#define OFF_AV 160
#define OFF_BQ 192
#define OFF_BK 1216
#define OFF_BV 1472

// scratch (static device arrays: allocation-free per harness rules)
__device__ float g_W[(size_t)N_PAD * D_IN];     // tf32-rounded packed W^T, [N, K] K-major
__device__ float g_Y[(size_t)M_TOT * N_PAD];    // GEMM result
__device__ float g_cos[SEQ * 64];
__device__ float g_sin[SEQ * 64];

__device__ __forceinline__ float to_tf32(float x) {
    uint32_t r;
    asm("cvt.rna.tf32.f32 %0, %1;" : "=r"(r) : "f"(x));
    return __uint_as_float(r);
}

// writes W^T: g_W[n*2048 + k]; rows n in [1728,1792) are zero pad
__global__ __launch_bounds__(256) void k_prep_w(
    const float* __restrict__ wa_q, const float* __restrict__ wa_k,
    const float* __restrict__ wa_v, const float* __restrict__ wb_q,
    const float* __restrict__ wb_k, const float* __restrict__ wb_v) {
    int i = blockIdx.x * 256 + threadIdx.x;
    if (i >= N_PAD * D_IN) return;
    int n = i >> 11;
    int k = i & 2047;
    float v;
    if      (n < 128)  v = wa_q[k * 128  + n];
    else if (n < 160)  v = wa_k[k * 32   + (n - 128)];
    else if (n < 192)  v = wa_v[k * 32   + (n - 160)];
    else if (n < 1216) v = wb_q[k * 1024 + (n - 192)];
    else if (n < 1472) v = wb_k[k * 256  + (n - 1216)];
    else if (n < 1728) v = wb_v[k * 256  + (n - 1472)];
    else               v = 0.0f;
    g_W[i] = to_tf32(v);
}

__global__ __launch_bounds__(256) void k_rope() {
    int i = blockIdx.x * 256 + threadIdx.x;
    if (i >= SEQ * 64) return;
    int s = i >> 6, d = i & 63;
    float ex   = -(float)d * (1.0f / 64.0f);
    float invf = exp2f(ex * 13.28771237954945f); // log2(10000)
    float f    = (float)s * invf;                 // fp32 product, like jnp.outer(f32)
    float sn, cs;
    sincosf(f, &sn, &cs);
    g_cos[i] = cs;
    g_sin[i] = sn;
}

// ============ GEMM: Y = X @ W, tf32 mma.sync, 128x128 CTA, 3-stage ========
#define BK 32
#define STAGES 3
#define STAGE_FLOATS (2 * 128 * BK)          // A tile + B tile
#define STAGE_BYTES  (STAGE_FLOATS * 4)      // 32768
#define GEMM_SMEM    (STAGES * STAGE_BYTES)  // 98304
#define NCHUNK (D_IN / BK)                   // 64

__device__ __forceinline__ void cp16(float* smem, const float* g) {
    uint32_t s = (uint32_t)__cvta_generic_to_shared(smem);
    asm volatile("cp.async.cg.shared.global [%0], [%1], 16;" :: "r"(s), "l"(g));
}

// swizzled word index for element (r, c) of a [128][32] tile
__device__ __forceinline__ int swz(int r, int c) {
    return r * 32 + (((c >> 2) ^ (r & 7)) << 2) + (c & 3);
}

// load A[128x32] from x and B[128x32] from g_W into stage (SW-swizzled)
__device__ __forceinline__ void load_chunk(float* st, const float* __restrict__ x,
                                           int bm, int bn, int c, int tid) {
    const float* gA = x   + (size_t)bm * 128 * D_IN + c * BK;
    const float* gB = g_W + (size_t)bn * 128 * D_IN + c * BK;
#pragma unroll
    for (int j = 0; j < 4; j++) {
        int u = tid + j * 256;
        int r = u >> 3, c16 = u & 7;
        int w = (r * 8 + (c16 ^ (r & 7))) * 4;
        cp16(st + w, gA + (size_t)r * D_IN + c16 * 4);
    }
#pragma unroll
    for (int j = 0; j < 4; j++) {
        int u = tid + j * 256;
        int r = u >> 3, c16 = u & 7;
        int w = (r * 8 + (c16 ^ (r & 7))) * 4;
        cp16(st + 4096 + w, gB + (size_t)r * D_IN + c16 * 4);
    }
}

__global__ __launch_bounds__(256, 2) void k_gemm(const float* __restrict__ x) {
    extern __shared__ float sm[];
    const int tid = threadIdx.x;
    const int lane = tid & 31, wid = tid >> 5;
    const int bn = blockIdx.x, bm = blockIdx.y;
    const int wm = (wid & 3) << 5;   // warp row base 0..96
    const int wn = (wid >> 2) << 6;  // warp col base 0 or 64
    const int gp = lane >> 2, u = lane & 3;

    float acc[2][8][4];
#pragma unroll
    for (int a = 0; a < 2; a++)
#pragma unroll
        for (int b = 0; b < 8; b++)
#pragma unroll
            for (int c = 0; c < 4; c++) acc[a][b][c] = 0.f;

    // preload chunks 0,1 into stages 0,1
#pragma unroll
    for (int c = 0; c < 2; c++) {
        load_chunk(sm + c * STAGE_FLOATS, x, bm, bn, c, tid);
        asm volatile("cp.async.commit_group;");
    }

    for (int i = 0; i < NCHUNK; i++) {
        const int st = i % STAGES;
        if (i + 2 < NCHUNK) {
            load_chunk(sm + ((i + 2) % STAGES) * STAGE_FLOATS, x, bm, bn, i + 2, tid);
            asm volatile("cp.async.commit_group;");
            asm volatile("cp.async.wait_group 2;");
        } else {
            asm volatile("cp.async.wait_group 0;");
        }
        __syncthreads();

        const float* A  = sm + st * STAGE_FLOATS;
        const float* Bs = A + 4096;
#pragma unroll
        for (int ks = 0; ks < 4; ks++) {
            const int c0 = ks * 8 + u;
            uint32_t afr[2][4], bfr[8][2];
#pragma unroll
            for (int tm = 0; tm < 2; tm++) {
                int r0 = wm + tm * 16 + gp;
                int r1 = r0 + 8;
                afr[tm][0] = __float_as_uint(to_tf32(A[swz(r0, c0)]));
                afr[tm][1] = __float_as_uint(to_tf32(A[swz(r1, c0)]));
                afr[tm][2] = __float_as_uint(to_tf32(A[swz(r0, c0 + 4)]));
                afr[tm][3] = __float_as_uint(to_tf32(A[swz(r1, c0 + 4)]));
            }
#pragma unroll
            for (int tn = 0; tn < 8; tn++) {
                int n = wn + tn * 8 + gp;
                bfr[tn][0] = __float_as_uint(Bs[swz(n, c0)]);
                bfr[tn][1] = __float_as_uint(Bs[swz(n, c0 + 4)]);
            }
#pragma unroll
            for (int tm = 0; tm < 2; tm++)
#pragma unroll
                for (int tn = 0; tn < 8; tn++) {
                    float* c = acc[tm][tn];
                    asm volatile(
                        "mma.sync.aligned.m16n8k8.row.col.f32.tf32.tf32.f32 "
                        "{%0,%1,%2,%3}, {%4,%5,%6,%7}, {%8,%9}, {%0,%1,%2,%3};"
                        : "+f"(c[0]), "+f"(c[1]), "+f"(c[2]), "+f"(c[3])
                        : "r"(afr[tm][0]), "r"(afr[tm][1]), "r"(afr[tm][2]), "r"(afr[tm][3]),
                          "r"(bfr[tn][0]), "r"(bfr[tn][1]));
                }
        }
        __syncthreads();
    }

#pragma unroll
    for (int tm = 0; tm < 2; tm++) {
        int row0 = bm * 128 + wm + tm * 16 + gp;
#pragma unroll
        for (int tn = 0; tn < 8; tn++) {
            int col = bn * 128 + wn + tn * 8 + 2 * u;
            *reinterpret_cast<float2*>(&g_Y[(size_t)row0 * N_PAD + col]) =
                make_float2(acc[tm][tn][0], acc[tm][tn][1]);
            *reinterpret_cast<float2*>(&g_Y[(size_t)(row0 + 8) * N_PAD + col]) =
                make_float2(acc[tm][tn][2], acc[tm][tn][3]);
        }
    }
}

// ---------------- epilogue: rope + rank contraction -----------------------
__global__ __launch_bounds__(256) void k_epi(float* __restrict__ out, int third) {
    const int t = blockIdx.x;          // token id 0..16383
    const int s = t & (SEQ - 1);       // position in sequence
    __shared__ float sY[N_TOT];
    __shared__ float sBq[1024];
    __shared__ float sBk[256];
    const int tid = threadIdx.x;
    const float* Yr = g_Y + (size_t)t * N_PAD;
    for (int i = tid; i < N_TOT; i += 256) sY[i] = Yr[i];
    __syncthreads();

    for (int p = tid; p < 512; p += 256) {
        int r = p >> 6, d = p & 63;
        float cs = g_cos[(s << 6) + d], sn = g_sin[(s << 6) + d];
        float x1 = sY[OFF_BQ + r * 128 + d];
        float x2 = sY[OFF_BQ + r * 128 + 64 + d];
        sBq[r * 128 + d]      = x1 * cs + x2 * sn;
        sBq[r * 128 + 64 + d] = x2 * cs - x1 * sn;
    }
    if (tid < 128) {
        int r = tid >> 6, d = tid & 63;
        float cs = g_cos[(s << 6) + d], sn = g_sin[(s << 6) + d];
        float x1 = sY[OFF_BK + r * 128 + d];
        float x2 = sY[OFF_BK + r * 128 + 64 + d];
        sBk[r * 128 + d]      = x1 * cs + x2 * sn;
        sBk[r * 128 + 64 + d] = x2 * cs - x1 * sn;
    }
    __syncthreads();

    const int d  = tid & 127;
    const int h0 = tid >> 7;
    float* oq = out;
    float* ok = out + (size_t)third;
    float* ov = out + (size_t)2 * third;
    const size_t base = (size_t)t * 2048 + d;
#pragma unroll
    for (int h = h0; h < 16; h += 2) {
        float q = 0.f;
#pragma unroll
        for (int r = 0; r < 8; r++) q += sY[OFF_AQ + h * 8 + r] * sBq[r * 128 + d];
        oq[base + h * 128] = q * 0.125f;
        float kk = sY[OFF_AK + h * 2] * sBk[d] + sY[OFF_AK + h * 2 + 1] * sBk[128 + d];
        ok[base + h * 128] = kk * 0.5f;
        float vv = sY[OFF_AV + h * 2] * sY[OFF_BV + d]
                 + sY[OFF_AV + h * 2 + 1] * sY[OFF_BV + 128 + d];
        ov[base + h * 128] = vv * 0.5f;
    }
}

extern "C" void kernel_launch(void* const* d_in, const int* in_sizes, int n_in,
                              void* d_out, int out_size) {
    const float* x    = (const float*)d_in[0];
    const float* wa_q = (const float*)d_in[1];
    const float* wa_k = (const float*)d_in[2];
    const float* wa_v = (const float*)d_in[3];
    const float* wb_q = (const float*)d_in[4];
    const float* wb_k = (const float*)d_in[5];
    const float* wb_v = (const float*)d_in[6];

    cudaFuncSetAttribute(k_gemm, cudaFuncAttributeMaxDynamicSharedMemorySize, GEMM_SMEM);

    k_prep_w<<<(N_PAD * D_IN + 255) / 256, 256>>>(wa_q, wa_k, wa_v, wb_q, wb_k, wb_v);
    k_rope<<<(SEQ * 64 + 255) / 256, 256>>>();
    dim3 grid(N_PAD / 128, M_TOT / 128);
    k_gemm<<<grid, 256, GEMM_SMEM>>>(x);
    k_epi<<<M_TOT, 256>>>((float*)d_out, out_size / 3);
}

// round 4
// speedup vs baseline: 1.0932x; 1.0932x over previous
#include <cuda_runtime.h>
#include <math.h>
#include <stdint.h>

#define M_TOT 16384
#define D_IN  2048
#define N_TOT 1728
#define N_PAD 1792
#define SEQ   4096

// column offsets inside a packed Y row
#define OFF_AQ 0
#define OFF_AK 128
#define OFF_AV 160
#define OFF_BQ 192
#define OFF_BK 1216
#define OFF_BV 1472

// scratch (static device arrays: allocation-free per harness rules)
__device__ float g_X[(size_t)M_TOT * D_IN];     // tf32-rounded X
__device__ float g_W[(size_t)N_PAD * D_IN];     // tf32-rounded packed W^T, [N, K] K-major
__device__ float g_Y[(size_t)M_TOT * N_PAD];    // GEMM result
__device__ float g_cos[SEQ * 64];
__device__ float g_sin[SEQ * 64];

__device__ __forceinline__ float to_tf32(float x) {
    uint32_t r;
    asm("cvt.rna.tf32.f32 %0, %1;" : "=r"(r) : "f"(x));
    return __uint_as_float(r);
}

__global__ __launch_bounds__(256) void k_prep_x(const float4* __restrict__ x) {
    int i = blockIdx.x * 256 + threadIdx.x;
    if (i >= M_TOT * D_IN / 4) return;
    float4 v = x[i];
    v.x = to_tf32(v.x); v.y = to_tf32(v.y);
    v.z = to_tf32(v.z); v.w = to_tf32(v.w);
    reinterpret_cast<float4*>(g_X)[i] = v;
}

// tiled transpose into g_W[n*2048+k]; rows n in [1728,1792) zero pad
__global__ void k_prep_w(
    const float* __restrict__ wa_q, const float* __restrict__ wa_k,
    const float* __restrict__ wa_v, const float* __restrict__ wb_q,
    const float* __restrict__ wb_k, const float* __restrict__ wb_v) {
    __shared__ float t[32][33];
    const int n0 = blockIdx.x * 32, k0 = blockIdx.y * 32;
    const int tx = threadIdx.x, ty = threadIdx.y;
    const float* src = nullptr; int ld = 0, nb = 0;
    if      (n0 < 128)  { src = wa_q; ld = 128;  nb = 0;    }
    else if (n0 < 160)  { src = wa_k; ld = 32;   nb = 128;  }
    else if (n0 < 192)  { src = wa_v; ld = 32;   nb = 160;  }
    else if (n0 < 1216) { src = wb_q; ld = 1024; nb = 192;  }
    else if (n0 < 1472) { src = wb_k; ld = 256;  nb = 1216; }
    else if (n0 < 1728) { src = wb_v; ld = 256;  nb = 1472; }
#pragma unroll
    for (int j = 0; j < 4; j++) {
        int r = ty + 8 * j;   // k row within tile
        float v = src ? src[(size_t)(k0 + r) * ld + (n0 - nb) + tx] : 0.f;
        t[r][tx] = to_tf32(v);
    }
    __syncthreads();
#pragma unroll
    for (int j = 0; j < 4; j++) {
        int r = ty + 8 * j;   // n row within tile
        g_W[(size_t)(n0 + r) * D_IN + k0 + tx] = t[tx][r];
    }
}

__global__ __launch_bounds__(256) void k_rope() {
    int i = blockIdx.x * 256 + threadIdx.x;
    if (i >= SEQ * 64) return;
    int s = i >> 6, d = i & 63;
    float ex   = -(float)d * (1.0f / 64.0f);
    float invf = exp2f(ex * 13.28771237954945f); // log2(10000)
    float f    = (float)s * invf;                 // fp32 product, like jnp.outer(f32)
    float sn, cs;
    sincosf(f, &sn, &cs);
    g_cos[i] = cs;
    g_sin[i] = sn;
}

// ==== GEMM: Y = X @ W, tf32 mma.sync, CTA 128x256, 8 warps x (64x64) ======
#define BK 32
#define BM 128
#define BN 256
#define STAGES 3
#define A_FLOATS (BM * BK)                    // 4096
#define STAGE_FLOATS ((BM + BN) * BK)         // 12288
#define GEMM_SMEM (STAGES * STAGE_FLOATS * 4) // 147456
#define NCHUNK (D_IN / BK)                    // 64

__device__ __forceinline__ void cp16(float* smem, const float* g) {
    uint32_t s = (uint32_t)__cvta_generic_to_shared(smem);
    asm volatile("cp.async.cg.shared.global [%0], [%1], 16;" :: "r"(s), "l"(g));
}

// swizzled word index for element (r, c) of a [rows][32] tile
__device__ __forceinline__ int swz(int r, int c) {
    return r * 32 + (((c >> 2) ^ (r & 7)) << 2) + (c & 3);
}

__device__ __forceinline__ void load_chunk(float* st, int bm, int bn, int c, int tid) {
    const float* gA = g_X + (size_t)bm * BM * D_IN + c * BK;
    const float* gB = g_W + (size_t)bn * BN * D_IN + c * BK;
#pragma unroll
    for (int j = 0; j < 4; j++) {                 // A: 128 rows x 8 chunks
        int u = tid + j * 256;
        int r = u >> 3, c16 = u & 7;
        int w = (r * 8 + (c16 ^ (r & 7))) * 4;
        cp16(st + w, gA + (size_t)r * D_IN + c16 * 4);
    }
#pragma unroll
    for (int j = 0; j < 8; j++) {                 // B: 256 rows x 8 chunks
        int u = tid + j * 256;
        int r = u >> 3, c16 = u & 7;
        int w = (r * 8 + (c16 ^ (r & 7))) * 4;
        cp16(st + A_FLOATS + w, gB + (size_t)r * D_IN + c16 * 4);
    }
}

__global__ __launch_bounds__(256, 1) void k_gemm() {
    extern __shared__ float sm[];
    const int tid = threadIdx.x;
    const int lane = tid & 31, wid = tid >> 5;
    const int bn = blockIdx.x, bm = blockIdx.y;
    const int wm = (wid & 1) << 6;    // 0 or 64
    const int wn = (wid >> 1) << 6;   // 0,64,128,192
    const int gp = lane >> 2, u = lane & 3;

    float acc[4][8][4];
#pragma unroll
    for (int a = 0; a < 4; a++)
#pragma unroll
        for (int b = 0; b < 8; b++)
#pragma unroll
            for (int c = 0; c < 4; c++) acc[a][b][c] = 0.f;

#pragma unroll
    for (int c = 0; c < 2; c++) {
        load_chunk(sm + c * STAGE_FLOATS, bm, bn, c, tid);
        asm volatile("cp.async.commit_group;");
    }

    for (int i = 0; i < NCHUNK; i++) {
        const int st = i % STAGES;
        if (i + 2 < NCHUNK) {
            load_chunk(sm + ((i + 2) % STAGES) * STAGE_FLOATS, bm, bn, i + 2, tid);
            asm volatile("cp.async.commit_group;");
            asm volatile("cp.async.wait_group 2;");
        } else {
            asm volatile("cp.async.wait_group 0;");
        }
        __syncthreads();

        const float* A  = sm + st * STAGE_FLOATS;
        const float* Bs = A + A_FLOATS;
#pragma unroll
        for (int ks = 0; ks < 4; ks++) {
            const int c0 = ks * 8 + u;
            uint32_t afr[4][4], bfr[8][2];
#pragma unroll
            for (int tm = 0; tm < 4; tm++) {
                int r0 = wm + tm * 16 + gp;
                int r1 = r0 + 8;
                afr[tm][0] = __float_as_uint(A[swz(r0, c0)]);
                afr[tm][1] = __float_as_uint(A[swz(r1, c0)]);
                afr[tm][2] = __float_as_uint(A[swz(r0, c0 + 4)]);
                afr[tm][3] = __float_as_uint(A[swz(r1, c0 + 4)]);
            }
#pragma unroll
            for (int tn = 0; tn < 8; tn++) {
                int n = wn + tn * 8 + gp;
                bfr[tn][0] = __float_as_uint(Bs[swz(n, c0)]);
                bfr[tn][1] = __float_as_uint(Bs[swz(n, c0 + 4)]);
            }
#pragma unroll
            for (int tm = 0; tm < 4; tm++)
#pragma unroll
                for (int tn = 0; tn < 8; tn++) {
                    float* c = acc[tm][tn];
                    asm volatile(
                        "mma.sync.aligned.m16n8k8.row.col.f32.tf32.tf32.f32 "
                        "{%0,%1,%2,%3}, {%4,%5,%6,%7}, {%8,%9}, {%0,%1,%2,%3};"
                        : "+f"(c[0]), "+f"(c[1]), "+f"(c[2]), "+f"(c[3])
                        : "r"(afr[tm][0]), "r"(afr[tm][1]), "r"(afr[tm][2]), "r"(afr[tm][3]),
                          "r"(bfr[tn][0]), "r"(bfr[tn][1]));
                }
        }
        __syncthreads();
    }

#pragma unroll
    for (int tm = 0; tm < 4; tm++) {
        int row0 = bm * BM + wm + tm * 16 + gp;
#pragma unroll
        for (int tn = 0; tn < 8; tn++) {
            int col = bn * BN + wn + tn * 8 + 2 * u;
            *reinterpret_cast<float2*>(&g_Y[(size_t)row0 * N_PAD + col]) =
                make_float2(acc[tm][tn][0], acc[tm][tn][1]);
            *reinterpret_cast<float2*>(&g_Y[(size_t)(row0 + 8) * N_PAD + col]) =
                make_float2(acc[tm][tn][2], acc[tm][tn][3]);
        }
    }
}

// ---------------- epilogue: rope + rank contraction -----------------------
__global__ __launch_bounds__(256) void k_epi(float* __restrict__ out, int third) {
    const int t = blockIdx.x;          // token id 0..16383
    const int s = t & (SEQ - 1);       // position in sequence
    __shared__ float sY[N_TOT];
    __shared__ float sBq[1024];
    __shared__ float sBk[256];
    const int tid = threadIdx.x;
    const float* Yr = g_Y + (size_t)t * N_PAD;
    for (int i = tid; i < N_TOT; i += 256) sY[i] = Yr[i];
    __syncthreads();

    for (int p = tid; p < 512; p += 256) {
        int r = p >> 6, d = p & 63;
        float cs = g_cos[(s << 6) + d], sn = g_sin[(s << 6) + d];
        float x1 = sY[OFF_BQ + r * 128 + d];
        float x2 = sY[OFF_BQ + r * 128 + 64 + d];
        sBq[r * 128 + d]      = x1 * cs + x2 * sn;
        sBq[r * 128 + 64 + d] = x2 * cs - x1 * sn;
    }
    if (tid < 128) {
        int r = tid >> 6, d = tid & 63;
        float cs = g_cos[(s << 6) + d], sn = g_sin[(s << 6) + d];
        float x1 = sY[OFF_BK + r * 128 + d];
        float x2 = sY[OFF_BK + r * 128 + 64 + d];
        sBk[r * 128 + d]      = x1 * cs + x2 * sn;
        sBk[r * 128 + 64 + d] = x2 * cs - x1 * sn;
    }
    __syncthreads();

    const int d  = tid & 127;
    const int h0 = tid >> 7;
    float* oq = out;
    float* ok = out + (size_t)third;
    float* ov = out + (size_t)2 * third;
    const size_t base = (size_t)t * 2048 + d;
#pragma unroll
    for (int h = h0; h < 16; h += 2) {
        float q = 0.f;
#pragma unroll
        for (int r = 0; r < 8; r++) q += sY[OFF_AQ + h * 8 + r] * sBq[r * 128 + d];
        oq[base + h * 128] = q * 0.125f;
        float kk = sY[OFF_AK + h * 2] * sBk[d] + sY[OFF_AK + h * 2 + 1] * sBk[128 + d];
        ok[base + h * 128] = kk * 0.5f;
        float vv = sY[OFF_AV + h * 2] * sY[OFF_BV + d]
                 + sY[OFF_AV + h * 2 + 1] * sY[OFF_BV + 128 + d];
        ov[base + h * 128] = vv * 0.5f;
    }
}

extern "C" void kernel_launch(void* const* d_in, const int* in_sizes, int n_in,
                              void* d_out, int out_size) {
    const float* x    = (const float*)d_in[0];
    const float* wa_q = (const float*)d_in[1];
    const float* wa_k = (const float*)d_in[2];
    const float* wa_v = (const float*)d_in[3];
    const float* wb_q = (const float*)d_in[4];
    const float* wb_k = (const float*)d_in[5];
    const float* wb_v = (const float*)d_in[6];

    cudaFuncSetAttribute(k_gemm, cudaFuncAttributeMaxDynamicSharedMemorySize, GEMM_SMEM);

    k_prep_x<<<(M_TOT * D_IN / 4 + 255) / 256, 256>>>((const float4*)x);
    dim3 wgrid(N_PAD / 32, D_IN / 32);
    k_prep_w<<<wgrid, dim3(32, 8)>>>(wa_q, wa_k, wa_v, wb_q, wb_k, wb_v);
    k_rope<<<(SEQ * 64 + 255) / 256, 256>>>();
    dim3 grid(N_PAD / BN, M_TOT / BM);
    k_gemm<<<grid, 256, GEMM_SMEM>>>();
    k_epi<<<M_TOT, 256>>>((float*)d_out, out_size / 3);
}